// round 14
// baseline (speedup 1.0000x reference)
#include <cuda_runtime.h>
#include <cuda_fp16.h>
#include <cstdint>
#include <math.h>

// Problem constants
#define B_   32
#define D_   512
#define NH_  8
#define DH_  64
#define DEPTH_ 8
#define MLP_ 2048
#define NC_  256
#define S_   512
#define M_   (B_*S_)   // 16384 rows

// ---------------- scratch (device globals; no allocation allowed) -------------
__device__ __align__(256) float  g_x[M_*D_];          // residual stream (fp32)
__device__ __align__(256) __half g_yh[M_*D_];         // LN out / attn out (half)
__device__ __align__(256) __half g_bigh[M_*MLP_];     // qkv (stride 1536) / mlp hidden
__device__ __align__(256) __half g_wqkvT[DEPTH_*1536*D_];
__device__ __align__(256) __half g_woT  [DEPTH_*D_*D_];
__device__ __align__(256) __half g_w1T  [DEPTH_*MLP_*D_];
__device__ __align__(256) __half g_w2T  [DEPTH_*D_*MLP_];

// ---------------- helpers ----------------------------------------------------
__device__ __forceinline__ uint32_t smem_u32(const void* p){
    return (uint32_t)__cvta_generic_to_shared(p);
}
__device__ __forceinline__ void cp16(uint32_t s, const void* g){
    asm volatile("cp.async.cg.shared.global [%0], [%1], 16;\n" :: "r"(s), "l"(g));
}
__device__ __forceinline__ void mma_f16(float* c, const uint32_t* a,
                                        uint32_t b0, uint32_t b1){
    asm volatile(
        "mma.sync.aligned.m16n8k16.row.col.f32.f16.f16.f32 "
        "{%0,%1,%2,%3}, {%4,%5,%6,%7}, {%8,%9}, {%0,%1,%2,%3};"
        : "+f"(c[0]), "+f"(c[1]), "+f"(c[2]), "+f"(c[3])
        : "r"(a[0]), "r"(a[1]), "r"(a[2]), "r"(a[3]), "r"(b0), "r"(b1));
}
__device__ __forceinline__ void ldsm_x4(uint32_t& r0, uint32_t& r1,
                                        uint32_t& r2, uint32_t& r3, uint32_t a){
    asm volatile("ldmatrix.sync.aligned.m8n8.x4.shared.b16 {%0,%1,%2,%3}, [%4];"
                 : "=r"(r0), "=r"(r1), "=r"(r2), "=r"(r3) : "r"(a));
}
__device__ __forceinline__ void ldsm_x4_t(uint32_t& r0, uint32_t& r1,
                                          uint32_t& r2, uint32_t& r3, uint32_t a){
    asm volatile("ldmatrix.sync.aligned.m8n8.x4.trans.shared.b16 {%0,%1,%2,%3}, [%4];"
                 : "=r"(r0), "=r"(r1), "=r"(r2), "=r"(r3) : "r"(a));
}
__device__ __forceinline__ float warpsum(float v){
    #pragma unroll
    for (int o = 16; o > 0; o >>= 1) v += __shfl_xor_sync(0xffffffffu, v, o);
    return v;
}
// exact-enough gelu: erf via Abramowitz-Stegun 7.1.26 (abs err 1.5e-7)
__device__ __forceinline__ float gelu_f(float x){
    float u = x * 0.70710678118654752f;
    float a = fabsf(u);
    float t = __fdividef(1.f, 1.f + 0.3275911f*a);
    float p = t*(0.254829592f + t*(-0.284496736f + t*(1.421413741f
              + t*(-1.453152027f + t*1.061405429f))));
    float erfv = 1.f - p*__expf(-a*a);
    erfv = copysignf(erfv, u);
    return 0.5f*x*(1.f + erfv);
}

// ---------------- fused weight transpose (all 4 weights, one launch) ----------
// w[K,N] fp32 -> wt[N,K] half; N-index < qn scaled by 0.125 (exact).
__global__ __launch_bounds__(256) void transpose_all(
    const float* __restrict__ qkv_w, const float* __restrict__ out_w,
    const float* __restrict__ mlp_w1, const float* __restrict__ mlp_w2,
    __half* __restrict__ wq, __half* __restrict__ wo,
    __half* __restrict__ w1, __half* __restrict__ w2)
{
    int idx = blockIdx.x;
    const float* w; __half* wt; int K, N, qn;
    if (idx < 6144){            w = qkv_w;  wt = wq; K = 512;  N = 1536; qn = 512; }
    else if (idx < 8192){ idx -= 6144;  w = out_w;  wt = wo; K = 512;  N = 512;  qn = 0; }
    else if (idx < 16384){ idx -= 8192; w = mlp_w1; wt = w1; K = 512;  N = 2048; qn = 0; }
    else {                idx -= 16384; w = mlp_w2; wt = w2; K = 2048; N = 512;  qn = 0; }
    const int ktiles = K >> 5, per_layer = (K >> 5) * (N >> 5);
    const int layer = idx / per_layer;
    const int rem   = idx % per_layer;
    const int k0 = (rem % ktiles) * 32;
    const int n0 = (rem / ktiles) * 32;

    __shared__ float t[32][33];
    const float* wl = w + (size_t)layer * K * N;
    __half* wtl = wt + (size_t)layer * K * N;
    const int tx = threadIdx.x & 31, ty = threadIdx.x >> 5;
    #pragma unroll
    for (int i = ty; i < 32; i += 8)
        t[i][tx] = wl[(size_t)(k0+i)*N + n0 + tx];
    __syncthreads();
    #pragma unroll
    for (int i = ty; i < 32; i += 8){
        float v = t[tx][i];
        if (n0 + i < qn) v *= 0.125f;
        wtl[(size_t)(n0+i)*K + k0 + tx] = __float2half_rn(v);
    }
}

// ---------------- embed + first LN (warp-per-row, fp32 out) -------------------
__global__ __launch_bounds__(128) void embed_ln_kernel(
    const float* __restrict__ z, const float* __restrict__ slots,
    const float* __restrict__ pe, const float* __restrict__ spe,
    const float* __restrict__ nw, const float* __restrict__ nb,
    float* __restrict__ x)
{
    const int warp = threadIdx.x >> 5, lane = threadIdx.x & 31;
    const int row = blockIdx.x * 4 + warp;     // 0..16383
    const int b   = row >> 9;
    const int tkn = row & 511;

    float4 v[4];
    if (tkn < NC_) {
        const float* sr = slots + ((size_t)b*NC_ + tkn)*D_;
        const float* pr = spe + (size_t)tkn*D_;
        #pragma unroll
        for (int j=0;j<4;j++){
            const int d0 = lane*4 + 128*j;
            float4 s4 = *(const float4*)(sr + d0);
            float4 p4 = *(const float4*)(pr + d0);
            v[j].x = s4.x+p4.x; v[j].y = s4.y+p4.y;
            v[j].z = s4.z+p4.z; v[j].w = s4.w+p4.w;
        }
    } else {
        const int p = tkn - NC_;
        const float* pr = pe + (size_t)p*D_;
        #pragma unroll
        for (int j=0;j<4;j++){
            const int d0 = lane*4 + 128*j;
            float4 p4 = *(const float4*)(pr + d0);
            v[j].x = z[((size_t)b*D_ + d0 + 0)*256 + p] + p4.x;
            v[j].y = z[((size_t)b*D_ + d0 + 1)*256 + p] + p4.y;
            v[j].z = z[((size_t)b*D_ + d0 + 2)*256 + p] + p4.z;
            v[j].w = z[((size_t)b*D_ + d0 + 3)*256 + p] + p4.w;
        }
    }
    float sum = 0.f;
    #pragma unroll
    for (int j=0;j<4;j++) sum += v[j].x + v[j].y + v[j].z + v[j].w;
    float mean = warpsum(sum) * (1.f/512.f);
    float ss = 0.f;
    #pragma unroll
    for (int j=0;j<4;j++){
        v[j].x -= mean; v[j].y -= mean; v[j].z -= mean; v[j].w -= mean;
        ss += v[j].x*v[j].x + v[j].y*v[j].y + v[j].z*v[j].z + v[j].w*v[j].w;
    }
    float rs = rsqrtf(warpsum(ss) * (1.f/512.f) + 1e-5f);
    #pragma unroll
    for (int j=0;j<4;j++){
        const int d0 = lane*4 + 128*j;
        const float4 wv = *(const float4*)(nw + d0);
        const float4 bv = *(const float4*)(nb + d0);
        float4 o;
        o.x = v[j].x*rs*wv.x + bv.x;
        o.y = v[j].y*rs*wv.y + bv.y;
        o.z = v[j].z*rs*wv.z + bv.z;
        o.w = v[j].w*rs*wv.w + bv.w;
        *(float4*)(x + (size_t)row*D_ + d0) = o;
    }
}

// ---------------- layernorm (warp-per-row, fp32 in -> half out) ---------------
__global__ __launch_bounds__(128) void ln_kernel(
    const float* __restrict__ xin, const float* __restrict__ w,
    const float* __restrict__ bia, __half* __restrict__ yout)
{
    const int warp = threadIdx.x >> 5, lane = threadIdx.x & 31;
    const size_t row = blockIdx.x * 4 + warp;
    const float* xr = xin + row*D_;

    float4 v[4];
    float sum = 0.f;
    #pragma unroll
    for (int j=0;j<4;j++){
        v[j] = *(const float4*)(xr + lane*4 + 128*j);
        sum += v[j].x + v[j].y + v[j].z + v[j].w;
    }
    float mean = warpsum(sum) * (1.f/512.f);
    float ss = 0.f;
    #pragma unroll
    for (int j=0;j<4;j++){
        v[j].x -= mean; v[j].y -= mean; v[j].z -= mean; v[j].w -= mean;
        ss += v[j].x*v[j].x + v[j].y*v[j].y + v[j].z*v[j].z + v[j].w*v[j].w;
    }
    float rs = rsqrtf(warpsum(ss) * (1.f/512.f) + 1e-5f);
    #pragma unroll
    for (int j=0;j<4;j++){
        const int d0 = lane*4 + 128*j;
        const float4 wv = *(const float4*)(w + d0);
        const float4 bv = *(const float4*)(bia + d0);
        __half2 h0 = __floats2half2_rn(v[j].x*rs*wv.x + bv.x, v[j].y*rs*wv.y + bv.y);
        __half2 h1 = __floats2half2_rn(v[j].z*rs*wv.z + bv.z, v[j].w*rs*wv.w + bv.w);
        uint2 pk; pk.x = *(uint32_t*)&h0; pk.y = *(uint32_t*)&h1;
        *(uint2*)(yout + row*D_ + d0) = pk;
    }
}

// ---------------- fp16 tensor-core GEMM (5-stage cp.async + ldmatrix) ---------
// C[M,N] = A[M,K] @ BT[N,K]^T, A/BT half. 128x128 tile, BK=32, 256 threads.
// EPI: 0 = store half, 1 = fp32 C += acc + bias, 2 = half C = gelu(acc + bias)
#define AS_STRIDE 40
#define AS_SZ (128*AS_STRIDE)     // halves
#define STAGE_HALVES (2*AS_SZ)
#define GEMM_STAGES 5
#define GEMM_SMEM_BYTES (GEMM_STAGES*STAGE_HALVES*2)

template<int EPI>
__global__ __launch_bounds__(256) void gemm_f16(
    const __half* __restrict__ A, const __half* __restrict__ BT,
    const float* __restrict__ bias, void* __restrict__ Cv,
    int M, int N, int K)
{
    extern __shared__ __half sm[];
    const int bm = blockIdx.y * 128;
    const int bn = blockIdx.x * 128;
    const int tid = threadIdx.x;
    const int warp = tid >> 5, lane = tid & 31;
    const int g = lane >> 2, tg = lane & 3;
    const int lm = lane & 15, lh = lane >> 4;
    const int wm = (warp & 1) << 6;
    const int wn = (warp >> 1) << 5;

    float c[4][4][4];
    #pragma unroll
    for (int i=0;i<4;i++)
        #pragma unroll
        for (int j=0;j<4;j++)
            #pragma unroll
            for (int r=0;r<4;r++) c[i][j][r] = 0.f;

    const int lr = tid >> 1;             // 0..127
    const int lc = (tid & 1) * 16;       // 0 or 16

    auto prefetch = [&](int kt, int st){
        __half* As = sm + st*STAGE_HALVES;
        __half* Bs = As + AS_SZ;
        const __half* ga = A  + (size_t)(bm+lr)*K + kt*32 + lc;
        const __half* gb = BT + (size_t)(bn+lr)*K + kt*32 + lc;
        cp16(smem_u32(As + lr*AS_STRIDE + lc),     ga);
        cp16(smem_u32(As + lr*AS_STRIDE + lc + 8), ga + 8);
        cp16(smem_u32(Bs + lr*AS_STRIDE + lc),     gb);
        cp16(smem_u32(Bs + lr*AS_STRIDE + lc + 8), gb + 8);
    };

    const int KT = K >> 5;
    prefetch(0,0); asm volatile("cp.async.commit_group;\n");
    prefetch(1,1); asm volatile("cp.async.commit_group;\n");
    prefetch(2,2); asm volatile("cp.async.commit_group;\n");
    prefetch(3,3); asm volatile("cp.async.commit_group;\n");

    int sc = 0;   // compute stage
    int sl = 4;   // next load stage
    for (int kt = 0; kt < KT; kt++){
        asm volatile("cp.async.wait_group 3;\n");
        __syncthreads();
        if (kt+4 < KT) prefetch(kt+4, sl);
        asm volatile("cp.async.commit_group;\n");

        const __half* As = sm + sc*STAGE_HALVES;
        const __half* Bs = As + AS_SZ;
        #pragma unroll
        for (int ks=0; ks<2; ks++){
            const int kb = ks*16;
            uint32_t af[4][4], bf[4][2];
            #pragma unroll
            for (int mf=0; mf<4; mf++){
                uint32_t a = smem_u32(As + (wm + mf*16 + lm)*AS_STRIDE + kb + lh*8);
                ldsm_x4(af[mf][0], af[mf][1], af[mf][2], af[mf][3], a);
            }
            #pragma unroll
            for (int np=0; np<2; np++){
                uint32_t a = smem_u32(Bs + (wn + np*16 + lm)*AS_STRIDE + kb + lh*8);
                ldsm_x4(bf[2*np][0], bf[2*np+1][0], bf[2*np][1], bf[2*np+1][1], a);
            }
            #pragma unroll
            for (int mf=0; mf<4; mf++)
                #pragma unroll
                for (int nf=0; nf<4; nf++)
                    mma_f16(c[mf][nf], af[mf], bf[nf][0], bf[nf][1]);
        }
        sc = (sc+1 == GEMM_STAGES) ? 0 : sc+1;
        sl = (sl+1 == GEMM_STAGES) ? 0 : sl+1;
    }

    // epilogue
    #pragma unroll
    for (int mf=0; mf<4; mf++){
        #pragma unroll
        for (int nf=0; nf<4; nf++){
            const int row = bm + wm + mf*16 + g;
            const int col = bn + wn + nf*8 + tg*2;
            #pragma unroll
            for (int half_=0; half_<2; half_++){
                const int r = row + half_*8;
                float v0 = c[mf][nf][half_*2+0];
                float v1 = c[mf][nf][half_*2+1];
                if (EPI == 0){
                    __half2 h = __floats2half2_rn(v0, v1);
                    *(uint32_t*)((__half*)Cv + (size_t)r*N + col) = *(uint32_t*)&h;
                } else if (EPI == 1){
                    float* p = (float*)Cv + (size_t)r*N + col;
                    p[0] += v0 + bias[col];
                    p[1] += v1 + bias[col+1];
                } else {
                    float t0 = gelu_f(v0 + bias[col]);
                    float t1 = gelu_f(v1 + bias[col+1]);
                    __half2 h = __floats2half2_rn(t0, t1);
                    *(uint32_t*)((__half*)Cv + (size_t)r*N + col) = *(uint32_t*)&h;
                }
            }
        }
    }
}

// ---------------- fp16 tensor-core causal flash attention (R7 config) ---------
// grid (S/64, NH, B), 128 threads (4 warps), 64-query tile, DH=64.
// Q is pre-scaled by 0.125 via the transposed qkv weights.
#define KS_STRIDE 72
#define VS_STRIDE 72

__global__ __launch_bounds__(128) void attn_kernel(
    const __half* __restrict__ qkv, __half* __restrict__ o)
{
    __shared__ __align__(16) __half Ks[64*KS_STRIDE];  // K tile; P region per warp
    __shared__ __align__(16) __half Vs[64*VS_STRIDE];  // V tile; Q staging at start

    const int qt = blockIdx.x;
    const int h  = blockIdx.y;
    const int b  = blockIdx.z;
    const int tid = threadIdx.x;
    const int w = tid >> 5, lane = tid & 31;
    const int g = lane >> 2, tg = lane & 3;
    const int wr = w * 16;
    const size_t base = (size_t)b * S_ * 1536;
    const int q0 = qt * 64;

    // ---- stage Q into Vs, pull A-fragments ----
    #pragma unroll
    for (int i=0;i<4;i++){
        int lin = tid + 128*i;
        int r = lin >> 3, c8 = (lin & 7) * 8;
        uint4 v = *(const uint4*)(qkv + base + (size_t)(q0+r)*1536 + h*64 + c8);
        *(uint4*)(Vs + r*VS_STRIDE + c8) = v;
    }
    __syncthreads();
    uint32_t aq[4][4];
    #pragma unroll
    for (int kg=0;kg<4;kg++){
        aq[kg][0] = *(const uint32_t*)&Vs[(wr+g  )*VS_STRIDE + 16*kg + 2*tg    ];
        aq[kg][1] = *(const uint32_t*)&Vs[(wr+g+8)*VS_STRIDE + 16*kg + 2*tg    ];
        aq[kg][2] = *(const uint32_t*)&Vs[(wr+g  )*VS_STRIDE + 16*kg + 2*tg + 8];
        aq[kg][3] = *(const uint32_t*)&Vs[(wr+g+8)*VS_STRIDE + 16*kg + 2*tg + 8];
    }

    float oacc[8][4];
    #pragma unroll
    for (int nf=0;nf<8;nf++)
        #pragma unroll
        for (int r=0;r<4;r++) oacc[nf][r] = 0.f;
    float mrow[2] = {-1e30f, -1e30f};
    float lrow[2] = {0.f, 0.f};

    for (int jt = 0; jt <= qt; jt++){
        __syncthreads();   // prior-iteration Ks/Vs reads complete
        const int j0 = jt * 64;
        #pragma unroll
        for (int i=0;i<4;i++){
            int lin = tid + 128*i;
            int r = lin >> 3, c8 = (lin & 7) * 8;
            const __half* kp = qkv + base + (size_t)(j0+r)*1536 + 512 + h*64 + c8;
            *(uint4*)(Ks + r*KS_STRIDE + c8) = *(const uint4*)kp;
            *(uint4*)(Vs + r*VS_STRIDE + c8) = *(const uint4*)(kp + 512);
        }
        __syncthreads();

        // ---- S = Q K^T ----
        float s[8][4];
        #pragma unroll
        for (int nf=0;nf<8;nf++)
            #pragma unroll
            for (int r=0;r<4;r++) s[nf][r] = 0.f;
        #pragma unroll
        for (int kg=0;kg<4;kg++){
            #pragma unroll
            for (int nf=0;nf<8;nf++){
                uint32_t b0 = *(const uint32_t*)&Ks[(nf*8+g)*KS_STRIDE + 16*kg + 2*tg    ];
                uint32_t b1 = *(const uint32_t*)&Ks[(nf*8+g)*KS_STRIDE + 16*kg + 2*tg + 8];
                mma_f16(s[nf], aq[kg], b0, b1);
            }
        }

        // ---- causal mask on the diagonal tile ----
        if (jt == qt){
            const int r0 = wr + g, r1 = wr + g + 8;
            #pragma unroll
            for (int nf=0;nf<8;nf++){
                int c = nf*8 + tg*2;
                if (c   > r0) s[nf][0] = -1e30f;
                if (c+1 > r0) s[nf][1] = -1e30f;
                if (c   > r1) s[nf][2] = -1e30f;
                if (c+1 > r1) s[nf][3] = -1e30f;
            }
        }

        // ---- online softmax ----
        float mx0 = -1e30f, mx1 = -1e30f;
        #pragma unroll
        for (int nf=0;nf<8;nf++){
            mx0 = fmaxf(mx0, fmaxf(s[nf][0], s[nf][1]));
            mx1 = fmaxf(mx1, fmaxf(s[nf][2], s[nf][3]));
        }
        mx0 = fmaxf(mx0, __shfl_xor_sync(0xffffffffu, mx0, 1));
        mx0 = fmaxf(mx0, __shfl_xor_sync(0xffffffffu, mx0, 2));
        mx1 = fmaxf(mx1, __shfl_xor_sync(0xffffffffu, mx1, 1));
        mx1 = fmaxf(mx1, __shfl_xor_sync(0xffffffffu, mx1, 2));
        float nm0 = fmaxf(mrow[0], mx0), nm1 = fmaxf(mrow[1], mx1);
        float cr0 = __expf(mrow[0] - nm0), cr1 = __expf(mrow[1] - nm1);
        float sum0 = 0.f, sum1 = 0.f;
        #pragma unroll
        for (int nf=0;nf<8;nf++){
            s[nf][0] = __expf(s[nf][0] - nm0);
            s[nf][1] = __expf(s[nf][1] - nm0);
            s[nf][2] = __expf(s[nf][2] - nm1);
            s[nf][3] = __expf(s[nf][3] - nm1);
            sum0 += s[nf][0] + s[nf][1];
            sum1 += s[nf][2] + s[nf][3];
        }
        sum0 += __shfl_xor_sync(0xffffffffu, sum0, 1);
        sum0 += __shfl_xor_sync(0xffffffffu, sum0, 2);
        sum1 += __shfl_xor_sync(0xffffffffu, sum1, 1);
        sum1 += __shfl_xor_sync(0xffffffffu, sum1, 2);
        lrow[0] = lrow[0]*cr0 + sum0;
        lrow[1] = lrow[1]*cr1 + sum1;
        mrow[0] = nm0; mrow[1] = nm1;
        #pragma unroll
        for (int nf=0;nf<8;nf++){
            oacc[nf][0] *= cr0; oacc[nf][1] *= cr0;
            oacc[nf][2] *= cr1; oacc[nf][3] *= cr1;
        }

        __syncthreads();   // all warps done reading Ks
        // ---- store P (half) into this warp's Ks slice ----
        __half* Ps = Ks + wr*KS_STRIDE;
        #pragma unroll
        for (int nf=0;nf<8;nf++){
            int c = nf*8 + tg*2;
            __half2 p0 = __floats2half2_rn(s[nf][0], s[nf][1]);
            __half2 p1 = __floats2half2_rn(s[nf][2], s[nf][3]);
            *(uint32_t*)(Ps +  g   *KS_STRIDE + c) = *(uint32_t*)&p0;
            *(uint32_t*)(Ps + (g+8)*KS_STRIDE + c) = *(uint32_t*)&p1;
        }
        __syncwarp();

        // ---- O += P V ----
        #pragma unroll
        for (int kg=0;kg<4;kg++){
            uint32_t ap[4];
            ap[0] = *(const uint32_t*)&Ps[ g   *KS_STRIDE + 16*kg + 2*tg    ];
            ap[1] = *(const uint32_t*)&Ps[(g+8)*KS_STRIDE + 16*kg + 2*tg    ];
            ap[2] = *(const uint32_t*)&Ps[ g   *KS_STRIDE + 16*kg + 2*tg + 8];
            ap[3] = *(const uint32_t*)&Ps[(g+8)*KS_STRIDE + 16*kg + 2*tg + 8];
            #pragma unroll
            for (int nh=0;nh<4;nh++){
                uint32_t addr = smem_u32(
                    Vs + (kg*16 + (lane & 15))*VS_STRIDE + nh*16 + (lane >> 4)*8);
                uint32_t b0,b1,b2,b3;
                ldsm_x4_t(b0,b1,b2,b3, addr);
                mma_f16(oacc[2*nh  ], ap, b0, b1);
                mma_f16(oacc[2*nh+1], ap, b2, b3);
            }
        }
    }

    // ---- write O (half) ----
    const float inv0 = 1.f / lrow[0], inv1 = 1.f / lrow[1];
    const int row0 = q0 + wr + g, row1 = row0 + 8;
    #pragma unroll
    for (int nf=0;nf<8;nf++){
        int c = h*64 + nf*8 + tg*2;
        __half2 h0 = __floats2half2_rn(oacc[nf][0]*inv0, oacc[nf][1]*inv0);
        __half2 h1 = __floats2half2_rn(oacc[nf][2]*inv1, oacc[nf][3]*inv1);
        *(uint32_t*)(o + (size_t)(b*S_ + row0)*D_ + c) = *(uint32_t*)&h0;
        *(uint32_t*)(o + (size_t)(b*S_ + row1)*D_ + c) = *(uint32_t*)&h1;
    }
}

// ---------------- output slice + transpose -----------------------------------
__global__ __launch_bounds__(256) void out_kernel(
    const float* __restrict__ x, float* __restrict__ out)
{
    const int idx = blockIdx.x * 256 + threadIdx.x;
    const int p = idx & 255;
    const int d = (idx >> 8) & 511;
    const int b = idx >> 17;
    out[idx] = x[((size_t)b*S_ + (NC_ - 1) + p)*D_ + d];
}

// ---------------- launch ------------------------------------------------------
extern "C" void kernel_launch(void* const* d_in, const int* in_sizes, int n_in,
                              void* d_out, int out_size)
{
    const float* z       = (const float*)d_in[0];
    const float* slots   = (const float*)d_in[1];
    const float* pos_emb = (const float*)d_in[2];
    const float* spe     = (const float*)d_in[3];
    const float* norm_w  = (const float*)d_in[4];
    const float* norm_b  = (const float*)d_in[5];
    const float* ln1_w   = (const float*)d_in[6];
    const float* ln1_b   = (const float*)d_in[7];
    const float* qkv_w   = (const float*)d_in[8];
    const float* out_w   = (const float*)d_in[9];
    const float* out_b   = (const float*)d_in[10];
    const float* ln2_w   = (const float*)d_in[11];
    const float* ln2_b   = (const float*)d_in[12];
    const float* mlp_w1  = (const float*)d_in[13];
    const float* mlp_b1  = (const float*)d_in[14];
    const float* mlp_w2  = (const float*)d_in[15];
    const float* mlp_b2  = (const float*)d_in[16];

    float *x;  __half *yh, *bigh, *wq, *wo, *w1, *w2;
    cudaGetSymbolAddress((void**)&x,    g_x);
    cudaGetSymbolAddress((void**)&yh,   g_yh);
    cudaGetSymbolAddress((void**)&bigh, g_bigh);
    cudaGetSymbolAddress((void**)&wq,   g_wqkvT);
    cudaGetSymbolAddress((void**)&wo,   g_woT);
    cudaGetSymbolAddress((void**)&w1,   g_w1T);
    cudaGetSymbolAddress((void**)&w2,   g_w2T);

    cudaFuncSetAttribute(gemm_f16<0>, cudaFuncAttributeMaxDynamicSharedMemorySize, GEMM_SMEM_BYTES);
    cudaFuncSetAttribute(gemm_f16<1>, cudaFuncAttributeMaxDynamicSharedMemorySize, GEMM_SMEM_BYTES);
    cudaFuncSetAttribute(gemm_f16<2>, cudaFuncAttributeMaxDynamicSharedMemorySize, GEMM_SMEM_BYTES);

    // one fused transpose launch (launch #0)
    transpose_all<<<24576, 256>>>(qkv_w, out_w, mlp_w1, mlp_w2, wq, wo, w1, w2);

    embed_ln_kernel<<<M_/4, 128>>>(z, slots, pos_emb, spe, norm_w, norm_b, x);

    for (int i = 0; i < DEPTH_; i++){
        ln_kernel<<<M_/4, 128>>>(x, ln1_w + i*D_, ln1_b + i*D_, yh);
        gemm_f16<0><<<dim3(12, 128), 256, GEMM_SMEM_BYTES>>>(
            yh, wq + (size_t)i*1536*D_, nullptr, bigh, M_, 1536, D_);
        attn_kernel<<<dim3(S_/64, NH_, B_), 128>>>(bigh, yh);
        gemm_f16<1><<<dim3(4, 128), 256, GEMM_SMEM_BYTES>>>(
            yh, wo + (size_t)i*D_*D_, out_b + i*D_, x, M_, D_, D_);
        ln_kernel<<<M_/4, 128>>>(x, ln2_w + i*D_, ln2_b + i*D_, yh);
        gemm_f16<2><<<dim3(16, 128), 256, GEMM_SMEM_BYTES>>>(
            yh, w1 + (size_t)i*MLP_*D_, mlp_b1 + i*MLP_, bigh, M_, MLP_, D_);
        gemm_f16<1><<<dim3(4, 128), 256, GEMM_SMEM_BYTES>>>(
            bigh, w2 + (size_t)i*D_*MLP_, mlp_b2 + i*D_, x, M_, D_, MLP_);
    }

    out_kernel<<<(B_*D_*256)/256, 256>>>(x, (float*)d_out);
}

// round 15
// speedup vs baseline: 1.0887x; 1.0887x over previous
#include <cuda_runtime.h>
#include <cuda_fp16.h>
#include <cstdint>
#include <math.h>

// Problem constants
#define B_   32
#define D_   512
#define NH_  8
#define DH_  64
#define DEPTH_ 8
#define MLP_ 2048
#define NC_  256
#define S_   512
#define M_   (B_*S_)   // 16384 rows

// ---------------- scratch (device globals; no allocation allowed) -------------
__device__ __align__(256) float  g_x[M_*D_];          // residual stream (fp32)
__device__ __align__(256) __half g_yh[M_*D_];         // LN out / attn out (half)
__device__ __align__(256) __half g_bigh[M_*MLP_];     // qkv (stride 1536) / mlp hidden
__device__ __align__(256) __half g_wqkvT[DEPTH_*1536*D_];
__device__ __align__(256) __half g_woT  [DEPTH_*D_*D_];
__device__ __align__(256) __half g_w1T  [DEPTH_*MLP_*D_];
__device__ __align__(256) __half g_w2T  [DEPTH_*D_*MLP_];

// ---------------- helpers ----------------------------------------------------
__device__ __forceinline__ uint32_t smem_u32(const void* p){
    return (uint32_t)__cvta_generic_to_shared(p);
}
__device__ __forceinline__ void cp16(uint32_t s, const void* g){
    asm volatile("cp.async.cg.shared.global [%0], [%1], 16;\n" :: "r"(s), "l"(g));
}
__device__ __forceinline__ void mma_f16(float* c, const uint32_t* a,
                                        uint32_t b0, uint32_t b1){
    asm volatile(
        "mma.sync.aligned.m16n8k16.row.col.f32.f16.f16.f32 "
        "{%0,%1,%2,%3}, {%4,%5,%6,%7}, {%8,%9}, {%0,%1,%2,%3};"
        : "+f"(c[0]), "+f"(c[1]), "+f"(c[2]), "+f"(c[3])
        : "r"(a[0]), "r"(a[1]), "r"(a[2]), "r"(a[3]), "r"(b0), "r"(b1));
}
__device__ __forceinline__ void ldsm_x4(uint32_t& r0, uint32_t& r1,
                                        uint32_t& r2, uint32_t& r3, uint32_t a){
    asm volatile("ldmatrix.sync.aligned.m8n8.x4.shared.b16 {%0,%1,%2,%3}, [%4];"
                 : "=r"(r0), "=r"(r1), "=r"(r2), "=r"(r3) : "r"(a));
}
__device__ __forceinline__ void ldsm_x4_t(uint32_t& r0, uint32_t& r1,
                                          uint32_t& r2, uint32_t& r3, uint32_t a){
    asm volatile("ldmatrix.sync.aligned.m8n8.x4.trans.shared.b16 {%0,%1,%2,%3}, [%4];"
                 : "=r"(r0), "=r"(r1), "=r"(r2), "=r"(r3) : "r"(a));
}
__device__ __forceinline__ float warpsum(float v){
    #pragma unroll
    for (int o = 16; o > 0; o >>= 1) v += __shfl_xor_sync(0xffffffffu, v, o);
    return v;
}
// exact-enough gelu: erf via Abramowitz-Stegun 7.1.26 (abs err 1.5e-7)
__device__ __forceinline__ float gelu_f(float x){
    float u = x * 0.70710678118654752f;
    float a = fabsf(u);
    float t = __fdividef(1.f, 1.f + 0.3275911f*a);
    float p = t*(0.254829592f + t*(-0.284496736f + t*(1.421413741f
              + t*(-1.453152027f + t*1.061405429f))));
    float erfv = 1.f - p*__expf(-a*a);
    erfv = copysignf(erfv, u);
    return 0.5f*x*(1.f + erfv);
}

// ---------------- fused weight transpose (all 4 weights, one launch) ----------
// w[K,N] fp32 -> wt[N,K] half; N-index < qn scaled by 0.125 (exact).
__global__ __launch_bounds__(256) void transpose_all(
    const float* __restrict__ qkv_w, const float* __restrict__ out_w,
    const float* __restrict__ mlp_w1, const float* __restrict__ mlp_w2,
    __half* __restrict__ wq, __half* __restrict__ wo,
    __half* __restrict__ w1, __half* __restrict__ w2)
{
    int idx = blockIdx.x;
    const float* w; __half* wt; int K, N, qn;
    if (idx < 6144){            w = qkv_w;  wt = wq; K = 512;  N = 1536; qn = 512; }
    else if (idx < 8192){ idx -= 6144;  w = out_w;  wt = wo; K = 512;  N = 512;  qn = 0; }
    else if (idx < 16384){ idx -= 8192; w = mlp_w1; wt = w1; K = 512;  N = 2048; qn = 0; }
    else {                idx -= 16384; w = mlp_w2; wt = w2; K = 2048; N = 512;  qn = 0; }
    const int ktiles = K >> 5, per_layer = (K >> 5) * (N >> 5);
    const int layer = idx / per_layer;
    const int rem   = idx % per_layer;
    const int k0 = (rem % ktiles) * 32;
    const int n0 = (rem / ktiles) * 32;

    __shared__ float t[32][33];
    const float* wl = w + (size_t)layer * K * N;
    __half* wtl = wt + (size_t)layer * K * N;
    const int tx = threadIdx.x & 31, ty = threadIdx.x >> 5;
    #pragma unroll
    for (int i = ty; i < 32; i += 8)
        t[i][tx] = wl[(size_t)(k0+i)*N + n0 + tx];
    __syncthreads();
    #pragma unroll
    for (int i = ty; i < 32; i += 8){
        float v = t[tx][i];
        if (n0 + i < qn) v *= 0.125f;
        wtl[(size_t)(n0+i)*K + k0 + tx] = __float2half_rn(v);
    }
}

// ---------------- embed + first LN (warp-per-row, fp32 out) -------------------
__global__ __launch_bounds__(128) void embed_ln_kernel(
    const float* __restrict__ z, const float* __restrict__ slots,
    const float* __restrict__ pe, const float* __restrict__ spe,
    const float* __restrict__ nw, const float* __restrict__ nb,
    float* __restrict__ x)
{
    const int warp = threadIdx.x >> 5, lane = threadIdx.x & 31;
    const int row = blockIdx.x * 4 + warp;     // 0..16383
    const int b   = row >> 9;
    const int tkn = row & 511;

    float4 v[4];
    if (tkn < NC_) {
        const float* sr = slots + ((size_t)b*NC_ + tkn)*D_;
        const float* pr = spe + (size_t)tkn*D_;
        #pragma unroll
        for (int j=0;j<4;j++){
            const int d0 = lane*4 + 128*j;
            float4 s4 = *(const float4*)(sr + d0);
            float4 p4 = *(const float4*)(pr + d0);
            v[j].x = s4.x+p4.x; v[j].y = s4.y+p4.y;
            v[j].z = s4.z+p4.z; v[j].w = s4.w+p4.w;
        }
    } else {
        const int p = tkn - NC_;
        const float* pr = pe + (size_t)p*D_;
        #pragma unroll
        for (int j=0;j<4;j++){
            const int d0 = lane*4 + 128*j;
            float4 p4 = *(const float4*)(pr + d0);
            v[j].x = z[((size_t)b*D_ + d0 + 0)*256 + p] + p4.x;
            v[j].y = z[((size_t)b*D_ + d0 + 1)*256 + p] + p4.y;
            v[j].z = z[((size_t)b*D_ + d0 + 2)*256 + p] + p4.z;
            v[j].w = z[((size_t)b*D_ + d0 + 3)*256 + p] + p4.w;
        }
    }
    float sum = 0.f;
    #pragma unroll
    for (int j=0;j<4;j++) sum += v[j].x + v[j].y + v[j].z + v[j].w;
    float mean = warpsum(sum) * (1.f/512.f);
    float ss = 0.f;
    #pragma unroll
    for (int j=0;j<4;j++){
        v[j].x -= mean; v[j].y -= mean; v[j].z -= mean; v[j].w -= mean;
        ss += v[j].x*v[j].x + v[j].y*v[j].y + v[j].z*v[j].z + v[j].w*v[j].w;
    }
    float rs = rsqrtf(warpsum(ss) * (1.f/512.f) + 1e-5f);
    #pragma unroll
    for (int j=0;j<4;j++){
        const int d0 = lane*4 + 128*j;
        const float4 wv = *(const float4*)(nw + d0);
        const float4 bv = *(const float4*)(nb + d0);
        float4 o;
        o.x = v[j].x*rs*wv.x + bv.x;
        o.y = v[j].y*rs*wv.y + bv.y;
        o.z = v[j].z*rs*wv.z + bv.z;
        o.w = v[j].w*rs*wv.w + bv.w;
        *(float4*)(x + (size_t)row*D_ + d0) = o;
    }
}

// ---------------- layernorm (warp-per-row, fp32 in -> half out) ---------------
__global__ __launch_bounds__(128) void ln_kernel(
    const float* __restrict__ xin, const float* __restrict__ w,
    const float* __restrict__ bia, __half* __restrict__ yout)
{
    const int warp = threadIdx.x >> 5, lane = threadIdx.x & 31;
    const size_t row = blockIdx.x * 4 + warp;
    const float* xr = xin + row*D_;

    float4 v[4];
    float sum = 0.f;
    #pragma unroll
    for (int j=0;j<4;j++){
        v[j] = *(const float4*)(xr + lane*4 + 128*j);
        sum += v[j].x + v[j].y + v[j].z + v[j].w;
    }
    float mean = warpsum(sum) * (1.f/512.f);
    float ss = 0.f;
    #pragma unroll
    for (int j=0;j<4;j++){
        v[j].x -= mean; v[j].y -= mean; v[j].z -= mean; v[j].w -= mean;
        ss += v[j].x*v[j].x + v[j].y*v[j].y + v[j].z*v[j].z + v[j].w*v[j].w;
    }
    float rs = rsqrtf(warpsum(ss) * (1.f/512.f) + 1e-5f);
    #pragma unroll
    for (int j=0;j<4;j++){
        const int d0 = lane*4 + 128*j;
        const float4 wv = *(const float4*)(w + d0);
        const float4 bv = *(const float4*)(bia + d0);
        __half2 h0 = __floats2half2_rn(v[j].x*rs*wv.x + bv.x, v[j].y*rs*wv.y + bv.y);
        __half2 h1 = __floats2half2_rn(v[j].z*rs*wv.z + bv.z, v[j].w*rs*wv.w + bv.w);
        uint2 pk; pk.x = *(uint32_t*)&h0; pk.y = *(uint32_t*)&h1;
        *(uint2*)(yout + row*D_ + d0) = pk;
    }
}

// ---------------- fp16 tensor-core GEMM (4-stage cp.async + ldmatrix, R12) ----
// C[M,N] = A[M,K] @ BT[N,K]^T, A/BT half. 128x128 tile, BK=32, 256 threads.
// EPI: 0 = store half, 1 = fp32 C += acc + bias, 2 = half C = gelu(acc + bias)
#define AS_STRIDE 40
#define AS_SZ (128*AS_STRIDE)     // halves
#define STAGE_HALVES (2*AS_SZ)
#define GEMM_SMEM_BYTES (4*STAGE_HALVES*2)

template<int EPI>
__global__ __launch_bounds__(256) void gemm_f16(
    const __half* __restrict__ A, const __half* __restrict__ BT,
    const float* __restrict__ bias, void* __restrict__ Cv,
    int M, int N, int K)
{
    extern __shared__ __half sm[];
    const int bm = blockIdx.y * 128;
    const int bn = blockIdx.x * 128;
    const int tid = threadIdx.x;
    const int warp = tid >> 5, lane = tid & 31;
    const int g = lane >> 2, tg = lane & 3;
    const int lm = lane & 15, lh = lane >> 4;
    const int wm = (warp & 1) << 6;
    const int wn = (warp >> 1) << 5;

    float c[4][4][4];
    #pragma unroll
    for (int i=0;i<4;i++)
        #pragma unroll
        for (int j=0;j<4;j++)
            #pragma unroll
            for (int r=0;r<4;r++) c[i][j][r] = 0.f;

    const int lr = tid >> 1;             // 0..127
    const int lc = (tid & 1) * 16;       // 0 or 16

    auto prefetch = [&](int kt, int st){
        __half* As = sm + st*STAGE_HALVES;
        __half* Bs = As + AS_SZ;
        const __half* ga = A  + (size_t)(bm+lr)*K + kt*32 + lc;
        const __half* gb = BT + (size_t)(bn+lr)*K + kt*32 + lc;
        cp16(smem_u32(As + lr*AS_STRIDE + lc),     ga);
        cp16(smem_u32(As + lr*AS_STRIDE + lc + 8), ga + 8);
        cp16(smem_u32(Bs + lr*AS_STRIDE + lc),     gb);
        cp16(smem_u32(Bs + lr*AS_STRIDE + lc + 8), gb + 8);
    };

    const int KT = K >> 5;
    prefetch(0,0); asm volatile("cp.async.commit_group;\n");
    prefetch(1,1); asm volatile("cp.async.commit_group;\n");
    prefetch(2,2); asm volatile("cp.async.commit_group;\n");

    for (int kt = 0; kt < KT; kt++){
        asm volatile("cp.async.wait_group 2;\n");
        __syncthreads();
        if (kt+3 < KT) prefetch(kt+3, (kt+3)&3);
        asm volatile("cp.async.commit_group;\n");

        const __half* As = sm + (kt&3)*STAGE_HALVES;
        const __half* Bs = As + AS_SZ;
        #pragma unroll
        for (int ks=0; ks<2; ks++){
            const int kb = ks*16;
            uint32_t af[4][4], bf[4][2];
            #pragma unroll
            for (int mf=0; mf<4; mf++){
                uint32_t a = smem_u32(As + (wm + mf*16 + lm)*AS_STRIDE + kb + lh*8);
                ldsm_x4(af[mf][0], af[mf][1], af[mf][2], af[mf][3], a);
            }
            #pragma unroll
            for (int np=0; np<2; np++){
                uint32_t a = smem_u32(Bs + (wn + np*16 + lm)*AS_STRIDE + kb + lh*8);
                ldsm_x4(bf[2*np][0], bf[2*np+1][0], bf[2*np][1], bf[2*np+1][1], a);
            }
            #pragma unroll
            for (int mf=0; mf<4; mf++)
                #pragma unroll
                for (int nf=0; nf<4; nf++)
                    mma_f16(c[mf][nf], af[mf], bf[nf][0], bf[nf][1]);
        }
    }

    // epilogue
    #pragma unroll
    for (int mf=0; mf<4; mf++){
        #pragma unroll
        for (int nf=0; nf<4; nf++){
            const int row = bm + wm + mf*16 + g;
            const int col = bn + wn + nf*8 + tg*2;
            #pragma unroll
            for (int half_=0; half_<2; half_++){
                const int r = row + half_*8;
                float v0 = c[mf][nf][half_*2+0];
                float v1 = c[mf][nf][half_*2+1];
                if (EPI == 0){
                    __half2 h = __floats2half2_rn(v0, v1);
                    *(uint32_t*)((__half*)Cv + (size_t)r*N + col) = *(uint32_t*)&h;
                } else if (EPI == 1){
                    float* p = (float*)Cv + (size_t)r*N + col;
                    p[0] += v0 + bias[col];
                    p[1] += v1 + bias[col+1];
                } else {
                    float t0 = gelu_f(v0 + bias[col]);
                    float t1 = gelu_f(v1 + bias[col+1]);
                    __half2 h = __floats2half2_rn(t0, t1);
                    *(uint32_t*)((__half*)Cv + (size_t)r*N + col) = *(uint32_t*)&h;
                }
            }
        }
    }
}

// ---------------- fp16 tensor-core causal flash attention ---------------------
// grid (S/64, NH, B), 128 threads (4 warps), 64-query tile, DH=64.
// Q pre-scaled by 0.125 via the transposed qkv weights.
// __launch_bounds__(128, 4): cap regs at 128 -> 4 blocks/SM (was 3 at 168 regs).
#define KS_STRIDE 72
#define VS_STRIDE 72

__global__ __launch_bounds__(128, 4) void attn_kernel(
    const __half* __restrict__ qkv, __half* __restrict__ o)
{
    __shared__ __align__(16) __half Ks[64*KS_STRIDE];  // K tile; P region per warp
    __shared__ __align__(16) __half Vs[64*VS_STRIDE];  // V tile; Q staging at start

    const int qt = blockIdx.x;
    const int h  = blockIdx.y;
    const int b  = blockIdx.z;
    const int tid = threadIdx.x;
    const int w = tid >> 5, lane = tid & 31;
    const int g = lane >> 2, tg = lane & 3;
    const int wr = w * 16;
    const size_t base = (size_t)b * S_ * 1536;
    const int q0 = qt * 64;

    // ---- stage Q into Vs, pull A-fragments ----
    #pragma unroll
    for (int i=0;i<4;i++){
        int lin = tid + 128*i;
        int r = lin >> 3, c8 = (lin & 7) * 8;
        uint4 v = *(const uint4*)(qkv + base + (size_t)(q0+r)*1536 + h*64 + c8);
        *(uint4*)(Vs + r*VS_STRIDE + c8) = v;
    }
    __syncthreads();
    uint32_t aq[4][4];
    #pragma unroll
    for (int kg=0;kg<4;kg++){
        aq[kg][0] = *(const uint32_t*)&Vs[(wr+g  )*VS_STRIDE + 16*kg + 2*tg    ];
        aq[kg][1] = *(const uint32_t*)&Vs[(wr+g+8)*VS_STRIDE + 16*kg + 2*tg    ];
        aq[kg][2] = *(const uint32_t*)&Vs[(wr+g  )*VS_STRIDE + 16*kg + 2*tg + 8];
        aq[kg][3] = *(const uint32_t*)&Vs[(wr+g+8)*VS_STRIDE + 16*kg + 2*tg + 8];
    }

    float oacc[8][4];
    #pragma unroll
    for (int nf=0;nf<8;nf++)
        #pragma unroll
        for (int r=0;r<4;r++) oacc[nf][r] = 0.f;
    float mrow[2] = {-1e30f, -1e30f};
    float lrow[2] = {0.f, 0.f};

    for (int jt = 0; jt <= qt; jt++){
        __syncthreads();   // prior-iteration Ks/Vs reads complete
        const int j0 = jt * 64;
        #pragma unroll
        for (int i=0;i<4;i++){
            int lin = tid + 128*i;
            int r = lin >> 3, c8 = (lin & 7) * 8;
            const __half* kp = qkv + base + (size_t)(j0+r)*1536 + 512 + h*64 + c8;
            *(uint4*)(Ks + r*KS_STRIDE + c8) = *(const uint4*)kp;
            *(uint4*)(Vs + r*VS_STRIDE + c8) = *(const uint4*)(kp + 512);
        }
        __syncthreads();

        // ---- S = Q K^T ----
        float s[8][4];
        #pragma unroll
        for (int nf=0;nf<8;nf++)
            #pragma unroll
            for (int r=0;r<4;r++) s[nf][r] = 0.f;
        #pragma unroll
        for (int kg=0;kg<4;kg++){
            #pragma unroll
            for (int nf=0;nf<8;nf++){
                uint32_t b0 = *(const uint32_t*)&Ks[(nf*8+g)*KS_STRIDE + 16*kg + 2*tg    ];
                uint32_t b1 = *(const uint32_t*)&Ks[(nf*8+g)*KS_STRIDE + 16*kg + 2*tg + 8];
                mma_f16(s[nf], aq[kg], b0, b1);
            }
        }

        // ---- causal mask on the diagonal tile ----
        if (jt == qt){
            const int r0 = wr + g, r1 = wr + g + 8;
            #pragma unroll
            for (int nf=0;nf<8;nf++){
                int c = nf*8 + tg*2;
                if (c   > r0) s[nf][0] = -1e30f;
                if (c+1 > r0) s[nf][1] = -1e30f;
                if (c   > r1) s[nf][2] = -1e30f;
                if (c+1 > r1) s[nf][3] = -1e30f;
            }
        }

        // ---- online softmax ----
        float mx0 = -1e30f, mx1 = -1e30f;
        #pragma unroll
        for (int nf=0;nf<8;nf++){
            mx0 = fmaxf(mx0, fmaxf(s[nf][0], s[nf][1]));
            mx1 = fmaxf(mx1, fmaxf(s[nf][2], s[nf][3]));
        }
        mx0 = fmaxf(mx0, __shfl_xor_sync(0xffffffffu, mx0, 1));
        mx0 = fmaxf(mx0, __shfl_xor_sync(0xffffffffu, mx0, 2));
        mx1 = fmaxf(mx1, __shfl_xor_sync(0xffffffffu, mx1, 1));
        mx1 = fmaxf(mx1, __shfl_xor_sync(0xffffffffu, mx1, 2));
        float nm0 = fmaxf(mrow[0], mx0), nm1 = fmaxf(mrow[1], mx1);
        float cr0 = __expf(mrow[0] - nm0), cr1 = __expf(mrow[1] - nm1);
        float sum0 = 0.f, sum1 = 0.f;
        #pragma unroll
        for (int nf=0;nf<8;nf++){
            s[nf][0] = __expf(s[nf][0] - nm0);
            s[nf][1] = __expf(s[nf][1] - nm0);
            s[nf][2] = __expf(s[nf][2] - nm1);
            s[nf][3] = __expf(s[nf][3] - nm1);
            sum0 += s[nf][0] + s[nf][1];
            sum1 += s[nf][2] + s[nf][3];
        }
        sum0 += __shfl_xor_sync(0xffffffffu, sum0, 1);
        sum0 += __shfl_xor_sync(0xffffffffu, sum0, 2);
        sum1 += __shfl_xor_sync(0xffffffffu, sum1, 1);
        sum1 += __shfl_xor_sync(0xffffffffu, sum1, 2);
        lrow[0] = lrow[0]*cr0 + sum0;
        lrow[1] = lrow[1]*cr1 + sum1;
        mrow[0] = nm0; mrow[1] = nm1;
        #pragma unroll
        for (int nf=0;nf<8;nf++){
            oacc[nf][0] *= cr0; oacc[nf][1] *= cr0;
            oacc[nf][2] *= cr1; oacc[nf][3] *= cr1;
        }

        __syncthreads();   // all warps done reading Ks
        // ---- store P (half) into this warp's Ks slice ----
        __half* Ps = Ks + wr*KS_STRIDE;
        #pragma unroll
        for (int nf=0;nf<8;nf++){
            int c = nf*8 + tg*2;
            __half2 p0 = __floats2half2_rn(s[nf][0], s[nf][1]);
            __half2 p1 = __floats2half2_rn(s[nf][2], s[nf][3]);
            *(uint32_t*)(Ps +  g   *KS_STRIDE + c) = *(uint32_t*)&p0;
            *(uint32_t*)(Ps + (g+8)*KS_STRIDE + c) = *(uint32_t*)&p1;
        }
        __syncwarp();

        // ---- O += P V ----
        #pragma unroll
        for (int kg=0;kg<4;kg++){
            uint32_t ap[4];
            ap[0] = *(const uint32_t*)&Ps[ g   *KS_STRIDE + 16*kg + 2*tg    ];
            ap[1] = *(const uint32_t*)&Ps[(g+8)*KS_STRIDE + 16*kg + 2*tg    ];
            ap[2] = *(const uint32_t*)&Ps[ g   *KS_STRIDE + 16*kg + 2*tg + 8];
            ap[3] = *(const uint32_t*)&Ps[(g+8)*KS_STRIDE + 16*kg + 2*tg + 8];
            #pragma unroll
            for (int nh=0;nh<4;nh++){
                uint32_t addr = smem_u32(
                    Vs + (kg*16 + (lane & 15))*VS_STRIDE + nh*16 + (lane >> 4)*8);
                uint32_t b0,b1,b2,b3;
                ldsm_x4_t(b0,b1,b2,b3, addr);
                mma_f16(oacc[2*nh  ], ap, b0, b1);
                mma_f16(oacc[2*nh+1], ap, b2, b3);
            }
        }
    }

    // ---- write O (half) ----
    const float inv0 = 1.f / lrow[0], inv1 = 1.f / lrow[1];
    const int row0 = q0 + wr + g, row1 = row0 + 8;
    #pragma unroll
    for (int nf=0;nf<8;nf++){
        int c = h*64 + nf*8 + tg*2;
        __half2 h0 = __floats2half2_rn(oacc[nf][0]*inv0, oacc[nf][1]*inv0);
        __half2 h1 = __floats2half2_rn(oacc[nf][2]*inv1, oacc[nf][3]*inv1);
        *(uint32_t*)(o + (size_t)(b*S_ + row0)*D_ + c) = *(uint32_t*)&h0;
        *(uint32_t*)(o + (size_t)(b*S_ + row1)*D_ + c) = *(uint32_t*)&h1;
    }
}

// ---------------- output slice + transpose -----------------------------------
__global__ __launch_bounds__(256) void out_kernel(
    const float* __restrict__ x, float* __restrict__ out)
{
    const int idx = blockIdx.x * 256 + threadIdx.x;
    const int p = idx & 255;
    const int d = (idx >> 8) & 511;
    const int b = idx >> 17;
    out[idx] = x[((size_t)b*S_ + (NC_ - 1) + p)*D_ + d];
}

// ---------------- launch ------------------------------------------------------
extern "C" void kernel_launch(void* const* d_in, const int* in_sizes, int n_in,
                              void* d_out, int out_size)
{
    const float* z       = (const float*)d_in[0];
    const float* slots   = (const float*)d_in[1];
    const float* pos_emb = (const float*)d_in[2];
    const float* spe     = (const float*)d_in[3];
    const float* norm_w  = (const float*)d_in[4];
    const float* norm_b  = (const float*)d_in[5];
    const float* ln1_w   = (const float*)d_in[6];
    const float* ln1_b   = (const float*)d_in[7];
    const float* qkv_w   = (const float*)d_in[8];
    const float* out_w   = (const float*)d_in[9];
    const float* out_b   = (const float*)d_in[10];
    const float* ln2_w   = (const float*)d_in[11];
    const float* ln2_b   = (const float*)d_in[12];
    const float* mlp_w1  = (const float*)d_in[13];
    const float* mlp_b1  = (const float*)d_in[14];
    const float* mlp_w2  = (const float*)d_in[15];
    const float* mlp_b2  = (const float*)d_in[16];

    float *x;  __half *yh, *bigh, *wq, *wo, *w1, *w2;
    cudaGetSymbolAddress((void**)&x,    g_x);
    cudaGetSymbolAddress((void**)&yh,   g_yh);
    cudaGetSymbolAddress((void**)&bigh, g_bigh);
    cudaGetSymbolAddress((void**)&wq,   g_wqkvT);
    cudaGetSymbolAddress((void**)&wo,   g_woT);
    cudaGetSymbolAddress((void**)&w1,   g_w1T);
    cudaGetSymbolAddress((void**)&w2,   g_w2T);

    cudaFuncSetAttribute(gemm_f16<0>, cudaFuncAttributeMaxDynamicSharedMemorySize, GEMM_SMEM_BYTES);
    cudaFuncSetAttribute(gemm_f16<1>, cudaFuncAttributeMaxDynamicSharedMemorySize, GEMM_SMEM_BYTES);
    cudaFuncSetAttribute(gemm_f16<2>, cudaFuncAttributeMaxDynamicSharedMemorySize, GEMM_SMEM_BYTES);

    // one fused transpose launch (launch #0)
    transpose_all<<<24576, 256>>>(qkv_w, out_w, mlp_w1, mlp_w2, wq, wo, w1, w2);

    embed_ln_kernel<<<M_/4, 128>>>(z, slots, pos_emb, spe, norm_w, norm_b, x);

    for (int i = 0; i < DEPTH_; i++){
        ln_kernel<<<M_/4, 128>>>(x, ln1_w + i*D_, ln1_b + i*D_, yh);
        gemm_f16<0><<<dim3(12, 128), 256, GEMM_SMEM_BYTES>>>(
            yh, wq + (size_t)i*1536*D_, nullptr, bigh, M_, 1536, D_);
        attn_kernel<<<dim3(S_/64, NH_, B_), 128>>>(bigh, yh);
        gemm_f16<1><<<dim3(4, 128), 256, GEMM_SMEM_BYTES>>>(
            yh, wo + (size_t)i*D_*D_, out_b + i*D_, x, M_, D_, D_);
        ln_kernel<<<M_/4, 128>>>(x, ln2_w + i*D_, ln2_b + i*D_, yh);
        gemm_f16<2><<<dim3(16, 128), 256, GEMM_SMEM_BYTES>>>(
            yh, w1 + (size_t)i*MLP_*D_, mlp_b1 + i*MLP_, bigh, M_, MLP_, D_);
        gemm_f16<1><<<dim3(4, 128), 256, GEMM_SMEM_BYTES>>>(
            bigh, w2 + (size_t)i*D_*MLP_, mlp_b2 + i*D_, x, M_, D_, MLP_);
    }

    out_kernel<<<(B_*D_*256)/256, 256>>>(x, (float*)d_out);
}

// round 16
// speedup vs baseline: 1.0968x; 1.0074x over previous
#include <cuda_runtime.h>
#include <cuda_fp16.h>
#include <cstdint>
#include <math.h>

// Problem constants
#define B_   32
#define D_   512
#define NH_  8
#define DH_  64
#define DEPTH_ 8
#define MLP_ 2048
#define NC_  256
#define S_   512
#define M_   (B_*S_)   // 16384 rows

// ---------------- scratch (device globals; no allocation allowed) -------------
__device__ __align__(256) float  g_x[M_*D_];          // residual stream (fp32)
__device__ __align__(256) __half g_yh[M_*D_];         // LN out / attn out (half)
__device__ __align__(256) __half g_bigh[M_*MLP_];     // qkv (stride 1536) / mlp hidden
__device__ __align__(256) __half g_wqkvT[DEPTH_*1536*D_];
__device__ __align__(256) __half g_woT  [DEPTH_*D_*D_];
__device__ __align__(256) __half g_w1T  [DEPTH_*MLP_*D_];
__device__ __align__(256) __half g_w2T  [DEPTH_*D_*MLP_];

// ---------------- helpers ----------------------------------------------------
__device__ __forceinline__ uint32_t smem_u32(const void* p){
    return (uint32_t)__cvta_generic_to_shared(p);
}
__device__ __forceinline__ void cp16(uint32_t s, const void* g){
    asm volatile("cp.async.cg.shared.global [%0], [%1], 16;\n" :: "r"(s), "l"(g));
}
__device__ __forceinline__ void mma_f16(float* c, const uint32_t* a,
                                        uint32_t b0, uint32_t b1){
    asm volatile(
        "mma.sync.aligned.m16n8k16.row.col.f32.f16.f16.f32 "
        "{%0,%1,%2,%3}, {%4,%5,%6,%7}, {%8,%9}, {%0,%1,%2,%3};"
        : "+f"(c[0]), "+f"(c[1]), "+f"(c[2]), "+f"(c[3])
        : "r"(a[0]), "r"(a[1]), "r"(a[2]), "r"(a[3]), "r"(b0), "r"(b1));
}
__device__ __forceinline__ void ldsm_x4(uint32_t& r0, uint32_t& r1,
                                        uint32_t& r2, uint32_t& r3, uint32_t a){
    asm volatile("ldmatrix.sync.aligned.m8n8.x4.shared.b16 {%0,%1,%2,%3}, [%4];"
                 : "=r"(r0), "=r"(r1), "=r"(r2), "=r"(r3) : "r"(a));
}
__device__ __forceinline__ void ldsm_x4_t(uint32_t& r0, uint32_t& r1,
                                          uint32_t& r2, uint32_t& r3, uint32_t a){
    asm volatile("ldmatrix.sync.aligned.m8n8.x4.trans.shared.b16 {%0,%1,%2,%3}, [%4];"
                 : "=r"(r0), "=r"(r1), "=r"(r2), "=r"(r3) : "r"(a));
}
__device__ __forceinline__ float warpsum(float v){
    #pragma unroll
    for (int o = 16; o > 0; o >>= 1) v += __shfl_xor_sync(0xffffffffu, v, o);
    return v;
}
// exact-enough gelu: erf via Abramowitz-Stegun 7.1.26 (abs err 1.5e-7)
__device__ __forceinline__ float gelu_f(float x){
    float u = x * 0.70710678118654752f;
    float a = fabsf(u);
    float t = __fdividef(1.f, 1.f + 0.3275911f*a);
    float p = t*(0.254829592f + t*(-0.284496736f + t*(1.421413741f
              + t*(-1.453152027f + t*1.061405429f))));
    float erfv = 1.f - p*__expf(-a*a);
    erfv = copysignf(erfv, u);
    return 0.5f*x*(1.f + erfv);
}

// ---------------- fused weight transpose (all 4 weights, one launch) ----------
// w[K,N] fp32 -> wt[N,K] half; N-index < qn scaled by 0.125 (exact).
__global__ __launch_bounds__(256) void transpose_all(
    const float* __restrict__ qkv_w, const float* __restrict__ out_w,
    const float* __restrict__ mlp_w1, const float* __restrict__ mlp_w2,
    __half* __restrict__ wq, __half* __restrict__ wo,
    __half* __restrict__ w1, __half* __restrict__ w2)
{
    int idx = blockIdx.x;
    const float* w; __half* wt; int K, N, qn;
    if (idx < 6144){            w = qkv_w;  wt = wq; K = 512;  N = 1536; qn = 512; }
    else if (idx < 8192){ idx -= 6144;  w = out_w;  wt = wo; K = 512;  N = 512;  qn = 0; }
    else if (idx < 16384){ idx -= 8192; w = mlp_w1; wt = w1; K = 512;  N = 2048; qn = 0; }
    else {                idx -= 16384; w = mlp_w2; wt = w2; K = 2048; N = 512;  qn = 0; }
    const int ktiles = K >> 5, per_layer = (K >> 5) * (N >> 5);
    const int layer = idx / per_layer;
    const int rem   = idx % per_layer;
    const int k0 = (rem % ktiles) * 32;
    const int n0 = (rem / ktiles) * 32;

    __shared__ float t[32][33];
    const float* wl = w + (size_t)layer * K * N;
    __half* wtl = wt + (size_t)layer * K * N;
    const int tx = threadIdx.x & 31, ty = threadIdx.x >> 5;
    #pragma unroll
    for (int i = ty; i < 32; i += 8)
        t[i][tx] = wl[(size_t)(k0+i)*N + n0 + tx];
    __syncthreads();
    #pragma unroll
    for (int i = ty; i < 32; i += 8){
        float v = t[tx][i];
        if (n0 + i < qn) v *= 0.125f;
        wtl[(size_t)(n0+i)*K + k0 + tx] = __float2half_rn(v);
    }
}

// ---------------- embed + first LN (warp-per-row, fp32 out) -------------------
__global__ __launch_bounds__(128) void embed_ln_kernel(
    const float* __restrict__ z, const float* __restrict__ slots,
    const float* __restrict__ pe, const float* __restrict__ spe,
    const float* __restrict__ nw, const float* __restrict__ nb,
    float* __restrict__ x)
{
    const int warp = threadIdx.x >> 5, lane = threadIdx.x & 31;
    const int row = blockIdx.x * 4 + warp;     // 0..16383
    const int b   = row >> 9;
    const int tkn = row & 511;

    float4 v[4];
    if (tkn < NC_) {
        const float* sr = slots + ((size_t)b*NC_ + tkn)*D_;
        const float* pr = spe + (size_t)tkn*D_;
        #pragma unroll
        for (int j=0;j<4;j++){
            const int d0 = lane*4 + 128*j;
            float4 s4 = *(const float4*)(sr + d0);
            float4 p4 = *(const float4*)(pr + d0);
            v[j].x = s4.x+p4.x; v[j].y = s4.y+p4.y;
            v[j].z = s4.z+p4.z; v[j].w = s4.w+p4.w;
        }
    } else {
        const int p = tkn - NC_;
        const float* pr = pe + (size_t)p*D_;
        #pragma unroll
        for (int j=0;j<4;j++){
            const int d0 = lane*4 + 128*j;
            float4 p4 = *(const float4*)(pr + d0);
            v[j].x = z[((size_t)b*D_ + d0 + 0)*256 + p] + p4.x;
            v[j].y = z[((size_t)b*D_ + d0 + 1)*256 + p] + p4.y;
            v[j].z = z[((size_t)b*D_ + d0 + 2)*256 + p] + p4.z;
            v[j].w = z[((size_t)b*D_ + d0 + 3)*256 + p] + p4.w;
        }
    }
    float sum = 0.f;
    #pragma unroll
    for (int j=0;j<4;j++) sum += v[j].x + v[j].y + v[j].z + v[j].w;
    float mean = warpsum(sum) * (1.f/512.f);
    float ss = 0.f;
    #pragma unroll
    for (int j=0;j<4;j++){
        v[j].x -= mean; v[j].y -= mean; v[j].z -= mean; v[j].w -= mean;
        ss += v[j].x*v[j].x + v[j].y*v[j].y + v[j].z*v[j].z + v[j].w*v[j].w;
    }
    float rs = rsqrtf(warpsum(ss) * (1.f/512.f) + 1e-5f);
    #pragma unroll
    for (int j=0;j<4;j++){
        const int d0 = lane*4 + 128*j;
        const float4 wv = *(const float4*)(nw + d0);
        const float4 bv = *(const float4*)(nb + d0);
        float4 o;
        o.x = v[j].x*rs*wv.x + bv.x;
        o.y = v[j].y*rs*wv.y + bv.y;
        o.z = v[j].z*rs*wv.z + bv.z;
        o.w = v[j].w*rs*wv.w + bv.w;
        *(float4*)(x + (size_t)row*D_ + d0) = o;
    }
}

// ---------------- layernorm (warp-per-row, fp32 in -> half out) ---------------
__global__ __launch_bounds__(128) void ln_kernel(
    const float* __restrict__ xin, const float* __restrict__ w,
    const float* __restrict__ bia, __half* __restrict__ yout)
{
    const int warp = threadIdx.x >> 5, lane = threadIdx.x & 31;
    const size_t row = blockIdx.x * 4 + warp;
    const float* xr = xin + row*D_;

    float4 v[4];
    float sum = 0.f;
    #pragma unroll
    for (int j=0;j<4;j++){
        v[j] = *(const float4*)(xr + lane*4 + 128*j);
        sum += v[j].x + v[j].y + v[j].z + v[j].w;
    }
    float mean = warpsum(sum) * (1.f/512.f);
    float ss = 0.f;
    #pragma unroll
    for (int j=0;j<4;j++){
        v[j].x -= mean; v[j].y -= mean; v[j].z -= mean; v[j].w -= mean;
        ss += v[j].x*v[j].x + v[j].y*v[j].y + v[j].z*v[j].z + v[j].w*v[j].w;
    }
    float rs = rsqrtf(warpsum(ss) * (1.f/512.f) + 1e-5f);
    #pragma unroll
    for (int j=0;j<4;j++){
        const int d0 = lane*4 + 128*j;
        const float4 wv = *(const float4*)(w + d0);
        const float4 bv = *(const float4*)(bia + d0);
        __half2 h0 = __floats2half2_rn(v[j].x*rs*wv.x + bv.x, v[j].y*rs*wv.y + bv.y);
        __half2 h1 = __floats2half2_rn(v[j].z*rs*wv.z + bv.z, v[j].w*rs*wv.w + bv.w);
        uint2 pk; pk.x = *(uint32_t*)&h0; pk.y = *(uint32_t*)&h1;
        *(uint2*)(yout + row*D_ + d0) = pk;
    }
}

// ---------------- fp16 tensor-core GEMM (4-stage cp.async + hoisted ldmatrix) -
// C[M,N] = A[M,K] @ BT[N,K]^T, A/BT half. 128x128 tile, BK=32, 256 threads.
// All 12 ldmatrix for the BK=32 step issue before the 32 mmas.
// EPI: 0 = store half, 1 = fp32 C += acc + bias, 2 = half C = gelu(acc + bias)
#define AS_STRIDE 40
#define AS_SZ (128*AS_STRIDE)     // halves
#define STAGE_HALVES (2*AS_SZ)
#define GEMM_SMEM_BYTES (4*STAGE_HALVES*2)

template<int EPI>
__global__ __launch_bounds__(256, 2) void gemm_f16(
    const __half* __restrict__ A, const __half* __restrict__ BT,
    const float* __restrict__ bias, void* __restrict__ Cv,
    int M, int N, int K)
{
    extern __shared__ __half sm[];
    const int bm = blockIdx.y * 128;
    const int bn = blockIdx.x * 128;
    const int tid = threadIdx.x;
    const int warp = tid >> 5, lane = tid & 31;
    const int g = lane >> 2, tg = lane & 3;
    const int lm = lane & 15, lh = lane >> 4;
    const int wm = (warp & 1) << 6;
    const int wn = (warp >> 1) << 5;

    float c[4][4][4];
    #pragma unroll
    for (int i=0;i<4;i++)
        #pragma unroll
        for (int j=0;j<4;j++)
            #pragma unroll
            for (int r=0;r<4;r++) c[i][j][r] = 0.f;

    const int lr = tid >> 1;             // 0..127
    const int lc = (tid & 1) * 16;       // 0 or 16

    auto prefetch = [&](int kt, int st){
        __half* As = sm + st*STAGE_HALVES;
        __half* Bs = As + AS_SZ;
        const __half* ga = A  + (size_t)(bm+lr)*K + kt*32 + lc;
        const __half* gb = BT + (size_t)(bn+lr)*K + kt*32 + lc;
        cp16(smem_u32(As + lr*AS_STRIDE + lc),     ga);
        cp16(smem_u32(As + lr*AS_STRIDE + lc + 8), ga + 8);
        cp16(smem_u32(Bs + lr*AS_STRIDE + lc),     gb);
        cp16(smem_u32(Bs + lr*AS_STRIDE + lc + 8), gb + 8);
    };

    const int KT = K >> 5;
    prefetch(0,0); asm volatile("cp.async.commit_group;\n");
    prefetch(1,1); asm volatile("cp.async.commit_group;\n");
    prefetch(2,2); asm volatile("cp.async.commit_group;\n");

    for (int kt = 0; kt < KT; kt++){
        asm volatile("cp.async.wait_group 2;\n");
        __syncthreads();
        if (kt+3 < KT) prefetch(kt+3, (kt+3)&3);
        asm volatile("cp.async.commit_group;\n");

        const __half* As = sm + (kt&3)*STAGE_HALVES;
        const __half* Bs = As + AS_SZ;

        // ---- hoisted fragment loads: all 12 ldmatrix for BK=32 ----
        uint32_t af[2][4][4], bf[2][4][2];
        #pragma unroll
        for (int ks=0; ks<2; ks++){
            const int kb = ks*16;
            #pragma unroll
            for (int mf=0; mf<4; mf++){
                uint32_t a = smem_u32(As + (wm + mf*16 + lm)*AS_STRIDE + kb + lh*8);
                ldsm_x4(af[ks][mf][0], af[ks][mf][1], af[ks][mf][2], af[ks][mf][3], a);
            }
            #pragma unroll
            for (int np=0; np<2; np++){
                uint32_t a = smem_u32(Bs + (wn + np*16 + lm)*AS_STRIDE + kb + lh*8);
                ldsm_x4(bf[ks][2*np][0], bf[ks][2*np+1][0],
                        bf[ks][2*np][1], bf[ks][2*np+1][1], a);
            }
        }
        // ---- 32 mmas ----
        #pragma unroll
        for (int ks=0; ks<2; ks++)
            #pragma unroll
            for (int mf=0; mf<4; mf++)
                #pragma unroll
                for (int nf=0; nf<4; nf++)
                    mma_f16(c[mf][nf], af[ks][mf], bf[ks][nf][0], bf[ks][nf][1]);
    }

    // epilogue
    #pragma unroll
    for (int mf=0; mf<4; mf++){
        #pragma unroll
        for (int nf=0; nf<4; nf++){
            const int row = bm + wm + mf*16 + g;
            const int col = bn + wn + nf*8 + tg*2;
            #pragma unroll
            for (int half_=0; half_<2; half_++){
                const int r = row + half_*8;
                float v0 = c[mf][nf][half_*2+0];
                float v1 = c[mf][nf][half_*2+1];
                if (EPI == 0){
                    __half2 h = __floats2half2_rn(v0, v1);
                    *(uint32_t*)((__half*)Cv + (size_t)r*N + col) = *(uint32_t*)&h;
                } else if (EPI == 1){
                    float* p = (float*)Cv + (size_t)r*N + col;
                    p[0] += v0 + bias[col];
                    p[1] += v1 + bias[col+1];
                } else {
                    float t0 = gelu_f(v0 + bias[col]);
                    float t1 = gelu_f(v1 + bias[col+1]);
                    __half2 h = __floats2half2_rn(t0, t1);
                    *(uint32_t*)((__half*)Cv + (size_t)r*N + col) = *(uint32_t*)&h;
                }
            }
        }
    }
}

// ---------------- fp16 tensor-core causal flash attention (R12 config) --------
// grid (S/64, NH, B), 128 threads (4 warps), 64-query tile, DH=64.
// Q is pre-scaled by 0.125 via the transposed qkv weights.
#define KS_STRIDE 72
#define VS_STRIDE 72

__global__ __launch_bounds__(128) void attn_kernel(
    const __half* __restrict__ qkv, __half* __restrict__ o)
{
    __shared__ __align__(16) __half Ks[64*KS_STRIDE];  // K tile; P region per warp
    __shared__ __align__(16) __half Vs[64*VS_STRIDE];  // V tile; Q staging at start

    const int qt = blockIdx.x;
    const int h  = blockIdx.y;
    const int b  = blockIdx.z;
    const int tid = threadIdx.x;
    const int w = tid >> 5, lane = tid & 31;
    const int g = lane >> 2, tg = lane & 3;
    const int wr = w * 16;
    const size_t base = (size_t)b * S_ * 1536;
    const int q0 = qt * 64;

    // ---- stage Q into Vs, pull A-fragments ----
    #pragma unroll
    for (int i=0;i<4;i++){
        int lin = tid + 128*i;
        int r = lin >> 3, c8 = (lin & 7) * 8;
        uint4 v = *(const uint4*)(qkv + base + (size_t)(q0+r)*1536 + h*64 + c8);
        *(uint4*)(Vs + r*VS_STRIDE + c8) = v;
    }
    __syncthreads();
    uint32_t aq[4][4];
    #pragma unroll
    for (int kg=0;kg<4;kg++){
        aq[kg][0] = *(const uint32_t*)&Vs[(wr+g  )*VS_STRIDE + 16*kg + 2*tg    ];
        aq[kg][1] = *(const uint32_t*)&Vs[(wr+g+8)*VS_STRIDE + 16*kg + 2*tg    ];
        aq[kg][2] = *(const uint32_t*)&Vs[(wr+g  )*VS_STRIDE + 16*kg + 2*tg + 8];
        aq[kg][3] = *(const uint32_t*)&Vs[(wr+g+8)*VS_STRIDE + 16*kg + 2*tg + 8];
    }

    float oacc[8][4];
    #pragma unroll
    for (int nf=0;nf<8;nf++)
        #pragma unroll
        for (int r=0;r<4;r++) oacc[nf][r] = 0.f;
    float mrow[2] = {-1e30f, -1e30f};
    float lrow[2] = {0.f, 0.f};

    for (int jt = 0; jt <= qt; jt++){
        __syncthreads();   // prior-iteration Ks/Vs reads complete
        const int j0 = jt * 64;
        #pragma unroll
        for (int i=0;i<4;i++){
            int lin = tid + 128*i;
            int r = lin >> 3, c8 = (lin & 7) * 8;
            const __half* kp = qkv + base + (size_t)(j0+r)*1536 + 512 + h*64 + c8;
            *(uint4*)(Ks + r*KS_STRIDE + c8) = *(const uint4*)kp;
            *(uint4*)(Vs + r*VS_STRIDE + c8) = *(const uint4*)(kp + 512);
        }
        __syncthreads();

        // ---- S = Q K^T ----
        float s[8][4];
        #pragma unroll
        for (int nf=0;nf<8;nf++)
            #pragma unroll
            for (int r=0;r<4;r++) s[nf][r] = 0.f;
        #pragma unroll
        for (int kg=0;kg<4;kg++){
            #pragma unroll
            for (int nf=0;nf<8;nf++){
                uint32_t b0 = *(const uint32_t*)&Ks[(nf*8+g)*KS_STRIDE + 16*kg + 2*tg    ];
                uint32_t b1 = *(const uint32_t*)&Ks[(nf*8+g)*KS_STRIDE + 16*kg + 2*tg + 8];
                mma_f16(s[nf], aq[kg], b0, b1);
            }
        }

        // ---- causal mask on the diagonal tile ----
        if (jt == qt){
            const int r0 = wr + g, r1 = wr + g + 8;
            #pragma unroll
            for (int nf=0;nf<8;nf++){
                int c = nf*8 + tg*2;
                if (c   > r0) s[nf][0] = -1e30f;
                if (c+1 > r0) s[nf][1] = -1e30f;
                if (c   > r1) s[nf][2] = -1e30f;
                if (c+1 > r1) s[nf][3] = -1e30f;
            }
        }

        // ---- online softmax ----
        float mx0 = -1e30f, mx1 = -1e30f;
        #pragma unroll
        for (int nf=0;nf<8;nf++){
            mx0 = fmaxf(mx0, fmaxf(s[nf][0], s[nf][1]));
            mx1 = fmaxf(mx1, fmaxf(s[nf][2], s[nf][3]));
        }
        mx0 = fmaxf(mx0, __shfl_xor_sync(0xffffffffu, mx0, 1));
        mx0 = fmaxf(mx0, __shfl_xor_sync(0xffffffffu, mx0, 2));
        mx1 = fmaxf(mx1, __shfl_xor_sync(0xffffffffu, mx1, 1));
        mx1 = fmaxf(mx1, __shfl_xor_sync(0xffffffffu, mx1, 2));
        float nm0 = fmaxf(mrow[0], mx0), nm1 = fmaxf(mrow[1], mx1);
        float cr0 = __expf(mrow[0] - nm0), cr1 = __expf(mrow[1] - nm1);
        float sum0 = 0.f, sum1 = 0.f;
        #pragma unroll
        for (int nf=0;nf<8;nf++){
            s[nf][0] = __expf(s[nf][0] - nm0);
            s[nf][1] = __expf(s[nf][1] - nm0);
            s[nf][2] = __expf(s[nf][2] - nm1);
            s[nf][3] = __expf(s[nf][3] - nm1);
            sum0 += s[nf][0] + s[nf][1];
            sum1 += s[nf][2] + s[nf][3];
        }
        sum0 += __shfl_xor_sync(0xffffffffu, sum0, 1);
        sum0 += __shfl_xor_sync(0xffffffffu, sum0, 2);
        sum1 += __shfl_xor_sync(0xffffffffu, sum1, 1);
        sum1 += __shfl_xor_sync(0xffffffffu, sum1, 2);
        lrow[0] = lrow[0]*cr0 + sum0;
        lrow[1] = lrow[1]*cr1 + sum1;
        mrow[0] = nm0; mrow[1] = nm1;
        #pragma unroll
        for (int nf=0;nf<8;nf++){
            oacc[nf][0] *= cr0; oacc[nf][1] *= cr0;
            oacc[nf][2] *= cr1; oacc[nf][3] *= cr1;
        }

        __syncthreads();   // all warps done reading Ks
        // ---- store P (half) into this warp's Ks slice ----
        __half* Ps = Ks + wr*KS_STRIDE;
        #pragma unroll
        for (int nf=0;nf<8;nf++){
            int c = nf*8 + tg*2;
            __half2 p0 = __floats2half2_rn(s[nf][0], s[nf][1]);
            __half2 p1 = __floats2half2_rn(s[nf][2], s[nf][3]);
            *(uint32_t*)(Ps +  g   *KS_STRIDE + c) = *(uint32_t*)&p0;
            *(uint32_t*)(Ps + (g+8)*KS_STRIDE + c) = *(uint32_t*)&p1;
        }
        __syncwarp();

        // ---- O += P V ----
        #pragma unroll
        for (int kg=0;kg<4;kg++){
            uint32_t ap[4];
            ap[0] = *(const uint32_t*)&Ps[ g   *KS_STRIDE + 16*kg + 2*tg    ];
            ap[1] = *(const uint32_t*)&Ps[(g+8)*KS_STRIDE + 16*kg + 2*tg    ];
            ap[2] = *(const uint32_t*)&Ps[ g   *KS_STRIDE + 16*kg + 2*tg + 8];
            ap[3] = *(const uint32_t*)&Ps[(g+8)*KS_STRIDE + 16*kg + 2*tg + 8];
            #pragma unroll
            for (int nh=0;nh<4;nh++){
                uint32_t addr = smem_u32(
                    Vs + (kg*16 + (lane & 15))*VS_STRIDE + nh*16 + (lane >> 4)*8);
                uint32_t b0,b1,b2,b3;
                ldsm_x4_t(b0,b1,b2,b3, addr);
                mma_f16(oacc[2*nh  ], ap, b0, b1);
                mma_f16(oacc[2*nh+1], ap, b2, b3);
            }
        }
    }

    // ---- write O (half) ----
    const float inv0 = 1.f / lrow[0], inv1 = 1.f / lrow[1];
    const int row0 = q0 + wr + g, row1 = row0 + 8;
    #pragma unroll
    for (int nf=0;nf<8;nf++){
        int c = h*64 + nf*8 + tg*2;
        __half2 h0 = __floats2half2_rn(oacc[nf][0]*inv0, oacc[nf][1]*inv0);
        __half2 h1 = __floats2half2_rn(oacc[nf][2]*inv1, oacc[nf][3]*inv1);
        *(uint32_t*)(o + (size_t)(b*S_ + row0)*D_ + c) = *(uint32_t*)&h0;
        *(uint32_t*)(o + (size_t)(b*S_ + row1)*D_ + c) = *(uint32_t*)&h1;
    }
}

// ---------------- output slice + transpose -----------------------------------
__global__ __launch_bounds__(256) void out_kernel(
    const float* __restrict__ x, float* __restrict__ out)
{
    const int idx = blockIdx.x * 256 + threadIdx.x;
    const int p = idx & 255;
    const int d = (idx >> 8) & 511;
    const int b = idx >> 17;
    out[idx] = x[((size_t)b*S_ + (NC_ - 1) + p)*D_ + d];
}

// ---------------- launch ------------------------------------------------------
extern "C" void kernel_launch(void* const* d_in, const int* in_sizes, int n_in,
                              void* d_out, int out_size)
{
    const float* z       = (const float*)d_in[0];
    const float* slots   = (const float*)d_in[1];
    const float* pos_emb = (const float*)d_in[2];
    const float* spe     = (const float*)d_in[3];
    const float* norm_w  = (const float*)d_in[4];
    const float* norm_b  = (const float*)d_in[5];
    const float* ln1_w   = (const float*)d_in[6];
    const float* ln1_b   = (const float*)d_in[7];
    const float* qkv_w   = (const float*)d_in[8];
    const float* out_w   = (const float*)d_in[9];
    const float* out_b   = (const float*)d_in[10];
    const float* ln2_w   = (const float*)d_in[11];
    const float* ln2_b   = (const float*)d_in[12];
    const float* mlp_w1  = (const float*)d_in[13];
    const float* mlp_b1  = (const float*)d_in[14];
    const float* mlp_w2  = (const float*)d_in[15];
    const float* mlp_b2  = (const float*)d_in[16];

    float *x;  __half *yh, *bigh, *wq, *wo, *w1, *w2;
    cudaGetSymbolAddress((void**)&x,    g_x);
    cudaGetSymbolAddress((void**)&yh,   g_yh);
    cudaGetSymbolAddress((void**)&bigh, g_bigh);
    cudaGetSymbolAddress((void**)&wq,   g_wqkvT);
    cudaGetSymbolAddress((void**)&wo,   g_woT);
    cudaGetSymbolAddress((void**)&w1,   g_w1T);
    cudaGetSymbolAddress((void**)&w2,   g_w2T);

    cudaFuncSetAttribute(gemm_f16<0>, cudaFuncAttributeMaxDynamicSharedMemorySize, GEMM_SMEM_BYTES);
    cudaFuncSetAttribute(gemm_f16<1>, cudaFuncAttributeMaxDynamicSharedMemorySize, GEMM_SMEM_BYTES);
    cudaFuncSetAttribute(gemm_f16<2>, cudaFuncAttributeMaxDynamicSharedMemorySize, GEMM_SMEM_BYTES);

    // one fused transpose launch (launch #0)
    transpose_all<<<24576, 256>>>(qkv_w, out_w, mlp_w1, mlp_w2, wq, wo, w1, w2);

    embed_ln_kernel<<<M_/4, 128>>>(z, slots, pos_emb, spe, norm_w, norm_b, x);

    for (int i = 0; i < DEPTH_; i++){
        ln_kernel<<<M_/4, 128>>>(x, ln1_w + i*D_, ln1_b + i*D_, yh);
        gemm_f16<0><<<dim3(12, 128), 256, GEMM_SMEM_BYTES>>>(
            yh, wq + (size_t)i*1536*D_, nullptr, bigh, M_, 1536, D_);
        attn_kernel<<<dim3(S_/64, NH_, B_), 128>>>(bigh, yh);
        gemm_f16<1><<<dim3(4, 128), 256, GEMM_SMEM_BYTES>>>(
            yh, wo + (size_t)i*D_*D_, out_b + i*D_, x, M_, D_, D_);
        ln_kernel<<<M_/4, 128>>>(x, ln2_w + i*D_, ln2_b + i*D_, yh);
        gemm_f16<2><<<dim3(16, 128), 256, GEMM_SMEM_BYTES>>>(
            yh, w1 + (size_t)i*MLP_*D_, mlp_b1 + i*MLP_, bigh, M_, MLP_, D_);
        gemm_f16<1><<<dim3(4, 128), 256, GEMM_SMEM_BYTES>>>(
            bigh, w2 + (size_t)i*D_*MLP_, mlp_b2 + i*D_, x, M_, D_, MLP_);
    }

    out_kernel<<<(B_*D_*256)/256, 256>>>(x, (float*)d_out);
}